// round 1
// baseline (speedup 1.0000x reference)
#include <cuda_runtime.h>

#define BATCH 16
#define LQ 1024
#define LK 2048
#define DIM 4096

// Scratch for S = QK^T, then overwritten with softmax(S). 134 MB.
__device__ float g_S[(size_t)BATCH * LQ * LK];

// ---------------------------------------------------------------------------
// GEMM1 (NT): S[b,m,n] = sum_d Q[b,m,d] * K[b,n,d]
// 64x64 tile, BK=16, 256 threads, 4x4 per thread, fp32.
// ---------------------------------------------------------------------------
__global__ __launch_bounds__(256) void qk_kernel(const float* __restrict__ Q,
                                                 const float* __restrict__ Km) {
  const int b  = blockIdx.z;
  const int m0 = blockIdx.y * 64;
  const int n0 = blockIdx.x * 64;
  const float* Qb = Q  + (size_t)b * LQ * DIM;
  const float* Kb = Km + (size_t)b * LK * DIM;
  float* Sb = g_S + (size_t)b * LQ * LK;

  __shared__ float As[16][68];  // [k][m], 68 = 64+4 pad (272B rows keep f4 align)
  __shared__ float Bs[16][68];  // [k][n]

  const int tid = threadIdx.x;
  const int lr = tid >> 2;          // 0..63 : row within tile for global load
  const int lc = (tid & 3) << 2;    // 0,4,8,12 : k-offset (float4)
  const int tm = (tid >> 4) << 2;   // 0..60 : m offset for compute
  const int tn = (tid & 15) << 2;   // 0..60 : n offset for compute

  float acc[4][4] = {};

  const float* aptr = Qb + (size_t)(m0 + lr) * DIM + lc;
  const float* bptr = Kb + (size_t)(n0 + lr) * DIM + lc;

  for (int d0 = 0; d0 < DIM; d0 += 16) {
    float4 a  = *(const float4*)(aptr + d0);
    float4 bv = *(const float4*)(bptr + d0);
    __syncthreads();
    As[lc + 0][lr] = a.x;  As[lc + 1][lr] = a.y;
    As[lc + 2][lr] = a.z;  As[lc + 3][lr] = a.w;
    Bs[lc + 0][lr] = bv.x; Bs[lc + 1][lr] = bv.y;
    Bs[lc + 2][lr] = bv.z; Bs[lc + 3][lr] = bv.w;
    __syncthreads();
#pragma unroll
    for (int kk = 0; kk < 16; ++kk) {
      float4 av = *(const float4*)&As[kk][tm];
      float4 bw = *(const float4*)&Bs[kk][tn];
      float am[4] = {av.x, av.y, av.z, av.w};
      float bn[4] = {bw.x, bw.y, bw.z, bw.w};
#pragma unroll
      for (int i = 0; i < 4; ++i)
#pragma unroll
        for (int j = 0; j < 4; ++j)
          acc[i][j] = fmaf(am[i], bn[j], acc[i][j]);
    }
  }
#pragma unroll
  for (int i = 0; i < 4; ++i) {
    float4 o = make_float4(acc[i][0], acc[i][1], acc[i][2], acc[i][3]);
    *(float4*)(Sb + (size_t)(m0 + tm + i) * LK + n0 + tn) = o;
  }
}

// ---------------------------------------------------------------------------
// Row softmax over LK=2048, in place in g_S. One block (256 thr) per row.
// ---------------------------------------------------------------------------
__global__ __launch_bounds__(256) void softmax_kernel() {
  float* row = g_S + (size_t)blockIdx.x * LK;
  const int t = threadIdx.x;

  float v[8];
  float m = -1e30f;
#pragma unroll
  for (int i = 0; i < 8; ++i) {
    v[i] = row[t + 256 * i];
    m = fmaxf(m, v[i]);
  }

  __shared__ float red[32];
  // warp max
#pragma unroll
  for (int o = 16; o; o >>= 1) m = fmaxf(m, __shfl_xor_sync(0xffffffffu, m, o));
  if ((t & 31) == 0) red[t >> 5] = m;
  __syncthreads();
  if (t < 32) {
    float x = (t < 8) ? red[t] : -1e30f;
#pragma unroll
    for (int o = 4; o; o >>= 1) x = fmaxf(x, __shfl_xor_sync(0xffffffffu, x, o));
    if (t == 0) red[0] = x;
  }
  __syncthreads();
  m = red[0];

  float s = 0.f;
#pragma unroll
  for (int i = 0; i < 8; ++i) {
    v[i] = __expf(v[i] - m);
    s += v[i];
  }
#pragma unroll
  for (int o = 16; o; o >>= 1) s += __shfl_xor_sync(0xffffffffu, s, o);
  __syncthreads();  // all reads of red[0] done before reuse
  if ((t & 31) == 0) red[t >> 5] = s;
  __syncthreads();
  if (t < 32) {
    float x = (t < 8) ? red[t] : 0.f;
#pragma unroll
    for (int o = 4; o; o >>= 1) x += __shfl_xor_sync(0xffffffffu, x, o);
    if (t == 0) red[1] = x;
  }
  __syncthreads();
  const float inv = 1.f / red[1];
#pragma unroll
  for (int i = 0; i < 8; ++i) row[t + 256 * i] = v[i] * inv;
}

// ---------------------------------------------------------------------------
// GEMM2 (NN): O[b,m,n] = sum_k P[b,m,k] * K[b,k,n]
// ---------------------------------------------------------------------------
__global__ __launch_bounds__(256) void pv_kernel(const float* __restrict__ Km,
                                                 float* __restrict__ O) {
  const int b  = blockIdx.z;
  const int m0 = blockIdx.y * 64;
  const int n0 = blockIdx.x * 64;
  const float* Pb = g_S + (size_t)b * LQ * LK;
  const float* Kb = Km  + (size_t)b * LK * DIM;
  float* Ob = O + (size_t)b * LQ * DIM;

  __shared__ float As[16][68];  // [k][m]
  __shared__ float Bs[16][68];  // [k][n]

  const int tid = threadIdx.x;
  const int lr = tid >> 2;          // A load: row 0..63
  const int lc = (tid & 3) << 2;    // A load: k off
  const int br = tid >> 4;          // B load: k row 0..15
  const int bc = (tid & 15) << 2;   // B load: n off 0..60
  const int tm = (tid >> 4) << 2;
  const int tn = (tid & 15) << 2;

  float acc[4][4] = {};

  for (int k0 = 0; k0 < LK; k0 += 16) {
    float4 a  = *(const float4*)(Pb + (size_t)(m0 + lr) * LK + k0 + lc);
    float4 bv = *(const float4*)(Kb + (size_t)(k0 + br) * DIM + n0 + bc);
    __syncthreads();
    As[lc + 0][lr] = a.x;  As[lc + 1][lr] = a.y;
    As[lc + 2][lr] = a.z;  As[lc + 3][lr] = a.w;
    *(float4*)&Bs[br][bc] = bv;
    __syncthreads();
#pragma unroll
    for (int kk = 0; kk < 16; ++kk) {
      float4 av = *(const float4*)&As[kk][tm];
      float4 bw = *(const float4*)&Bs[kk][tn];
      float am[4] = {av.x, av.y, av.z, av.w};
      float bn[4] = {bw.x, bw.y, bw.z, bw.w};
#pragma unroll
      for (int i = 0; i < 4; ++i)
#pragma unroll
        for (int j = 0; j < 4; ++j)
          acc[i][j] = fmaf(am[i], bn[j], acc[i][j]);
    }
  }
#pragma unroll
  for (int i = 0; i < 4; ++i) {
    float4 o = make_float4(acc[i][0], acc[i][1], acc[i][2], acc[i][3]);
    *(float4*)(Ob + (size_t)(m0 + tm + i) * DIM + n0 + tn) = o;
  }
}

// ---------------------------------------------------------------------------
extern "C" void kernel_launch(void* const* d_in, const int* in_sizes, int n_in,
                              void* d_out, int out_size) {
  const float* Q = (const float*)d_in[0];
  const float* K = (const float*)d_in[1];
  float* O = (float*)d_out;

  dim3 g1(LK / 64, LQ / 64, BATCH);   // 32 x 16 x 16
  qk_kernel<<<g1, 256>>>(Q, K);

  softmax_kernel<<<BATCH * LQ, 256>>>();

  dim3 g2(DIM / 64, LQ / 64, BATCH);  // 64 x 16 x 16
  pv_kernel<<<g2, 256>>>(K, O);
}

// round 5
// speedup vs baseline: 2.6465x; 2.6465x over previous
#include <cuda_runtime.h>
#include <cuda_bf16.h>
#include <cstdint>

#define BATCH 16
#define LQ 1024
#define LK 2048
#define DIM 4096

using bf16 = __nv_bfloat16;

// ---------------- scratch (static device allocations) ----------------
__device__ bf16 g_Qh[(size_t)BATCH * LQ * DIM];   // 128 MiB
__device__ bf16 g_Ql[(size_t)BATCH * LQ * DIM];   // 128 MiB
__device__ bf16 g_Kh[(size_t)BATCH * LK * DIM];   // 256 MiB
__device__ bf16 g_Kl[(size_t)BATCH * LK * DIM];   // 256 MiB
__device__ bf16 g_Kth[(size_t)BATCH * DIM * LK];  // 256 MiB (K^T, hi)
__device__ bf16 g_Ktl[(size_t)BATCH * DIM * LK];  // 256 MiB (K^T, lo)
__device__ float g_S[(size_t)BATCH * LQ * LK];    // 128 MiB
__device__ bf16 g_Ph[(size_t)BATCH * LQ * LK];    // 64 MiB
__device__ bf16 g_Pl[(size_t)BATCH * LQ * LK];    // 64 MiB

// ---------------- helpers ----------------
__device__ __forceinline__ uint32_t smem_u32(const void* p) {
  uint32_t a;
  asm("{ .reg .u64 t; cvta.to.shared.u64 t, %1; cvt.u32.u64 %0, t; }"
      : "=r"(a) : "l"(p));
  return a;
}
__device__ __forceinline__ void cp16(uint32_t s, const void* g) {
  asm volatile("cp.async.cg.shared.global [%0], [%1], 16;" :: "r"(s), "l"(g));
}
#define CP_COMMIT() asm volatile("cp.async.commit_group;" ::: "memory")
#define CP_WAIT2()  asm volatile("cp.async.wait_group 2;" ::: "memory")

#define LDSM4(R0, R1, R2, R3, A)                                              \
  asm volatile("ldmatrix.sync.aligned.m8n8.x4.shared.b16 {%0,%1,%2,%3}, [%4];"\
               : "=r"(R0), "=r"(R1), "=r"(R2), "=r"(R3) : "r"(A))

__device__ __forceinline__ void mma16816(float* c, const uint32_t* a,
                                         const uint32_t* b) {
  asm volatile(
      "mma.sync.aligned.m16n8k16.row.col.f32.bf16.bf16.f32 "
      "{%0,%1,%2,%3}, {%4,%5,%6,%7}, {%8,%9}, {%0,%1,%2,%3};"
      : "+f"(c[0]), "+f"(c[1]), "+f"(c[2]), "+f"(c[3])
      : "r"(a[0]), "r"(a[1]), "r"(a[2]), "r"(a[3]), "r"(b[0]), "r"(b[1]));
}

// ---------------- smem layout (per pipeline stage) ----------------
// A tile 128x32 bf16 (8 KiB) x{h,l}, B tile 128x32 bf16 x{h,l} = 32 KiB/stage
#define OFF_AH 0
#define OFF_AL 8192
#define OFF_BH 16384
#define OFF_BL 24576
#define STAGE_BYTES 32768
#define NSTAGE 4
#define SMEM_ALLOC (NSTAGE * STAGE_BYTES)

// ---------------- conversion kernels ----------------
__device__ __forceinline__ uint32_t pk2(bf16 a, bf16 b) {
  __nv_bfloat162 t{a, b};
  return *reinterpret_cast<uint32_t*>(&t);
}

__global__ __launch_bounds__(256) void convert_q(const float4* __restrict__ Q) {
  size_t i = (size_t)blockIdx.x * 256 + threadIdx.x;
  float4 v = Q[i];
  float f[4] = {v.x, v.y, v.z, v.w};
  bf16 h[4], l[4];
#pragma unroll
  for (int j = 0; j < 4; ++j) {
    h[j] = __float2bfloat16(f[j]);
    l[j] = __float2bfloat16(f[j] - __bfloat162float(h[j]));
  }
  *(uint2*)(g_Qh + 4 * i) = make_uint2(pk2(h[0], h[1]), pk2(h[2], h[3]));
  *(uint2*)(g_Ql + 4 * i) = make_uint2(pk2(l[0], l[1]), pk2(l[2], l[3]));
}

// K -> Kh/Kl (row-major) and Kth/Ktl (transposed [d][k]) in one pass
__global__ __launch_bounds__(256) void convert_kt(const float* __restrict__ K) {
  __shared__ float tile[32][33];
  const int b = blockIdx.z, k0 = blockIdx.y * 32, d0 = blockIdx.x * 32;
  const float* Kb = K + (size_t)b * LK * DIM;
  bf16* Khb = g_Kh + (size_t)b * LK * DIM;
  bf16* Klb = g_Kl + (size_t)b * LK * DIM;
  bf16* Kthb = g_Kth + (size_t)b * DIM * LK;
  bf16* Ktlb = g_Ktl + (size_t)b * DIM * LK;
  const int tx = threadIdx.x, ty = threadIdx.y;
#pragma unroll
  for (int i = 0; i < 4; ++i) {
    int k = k0 + ty + 8 * i;
    float v = Kb[(size_t)k * DIM + d0 + tx];
    bf16 h = __float2bfloat16(v);
    Khb[(size_t)k * DIM + d0 + tx] = h;
    Klb[(size_t)k * DIM + d0 + tx] = __float2bfloat16(v - __bfloat162float(h));
    tile[ty + 8 * i][tx] = v;
  }
  __syncthreads();
#pragma unroll
  for (int i = 0; i < 4; ++i) {
    int d = d0 + ty + 8 * i;
    float v = tile[tx][ty + 8 * i];
    bf16 h = __float2bfloat16(v);
    Kthb[(size_t)d * LK + k0 + tx] = h;
    Ktlb[(size_t)d * LK + k0 + tx] = __float2bfloat16(v - __bfloat162float(h));
  }
}

// ---------------- split-bf16 NT GEMM via mma.sync (HMMA) ----------------
// C[m][n] = sum_k (Ah+Al)[m][k]*(Bh+Bl)[n][k]  (3 products: hh, hl, lh)
// CTA 128x128, BK=32, 256 thr (8 warps as 2Mx4N of 64x32), 4-stage cp.async.
__device__ __forceinline__ void load_stage(uint32_t stg, const bf16* Ah,
                                           const bf16* Al, const bf16* Bh,
                                           const bf16* Bl, int kdim, int koff,
                                           int tid) {
#pragma unroll
  for (int it = 0; it < 2; ++it) {
    int idx = tid + 256 * it;            // 0..511 = 128 rows x 4 chunks(16B)
    int r = idx >> 2, c = idx & 3;
    uint32_t so = (uint32_t)(r * 64 + ((c ^ ((r >> 1) & 3)) << 4));
    size_t go = (size_t)r * kdim + koff + c * 8;
    cp16(stg + OFF_AH + so, Ah + go);
    cp16(stg + OFF_AL + so, Al + go);
    cp16(stg + OFF_BH + so, Bh + go);
    cp16(stg + OFF_BL + so, Bl + go);
  }
}

template <int KDIM, int LDC>
__device__ __forceinline__ void mma_body(const bf16* __restrict__ Ahg,
                                         const bf16* __restrict__ Alg,
                                         const bf16* __restrict__ Bhg,
                                         const bf16* __restrict__ Blg,
                                         float* __restrict__ C, size_t aBatch,
                                         size_t bBatch, size_t cBatch) {
  extern __shared__ char smem_raw[];
  const uint32_t smem = smem_u32(smem_raw);
  const int tid = threadIdx.x;
  const int lane = tid & 31, wid = tid >> 5;
  const int wm = wid & 1, wn = wid >> 1;   // warp tile 64x32 in 2x4 grid
  const int b = blockIdx.z;
  const int n0 = blockIdx.x * 128, m0 = blockIdx.y * 128;

  const bf16* Ah = Ahg + (size_t)b * aBatch + (size_t)m0 * KDIM;
  const bf16* Al = Alg + (size_t)b * aBatch + (size_t)m0 * KDIM;
  const bf16* Bh = Bhg + (size_t)b * bBatch + (size_t)n0 * KDIM;
  const bf16* Bl = Blg + (size_t)b * bBatch + (size_t)n0 * KDIM;

  // ldmatrix lane addressing (x4): g0: rows 0-7 k0-7 | g1: rows 8-15 k0-7
  //                                g2: rows 0-7 k8-15| g3: rows 8-15 k8-15
  const int g = lane >> 3, rr = lane & 7;
  const int grow = ((g & 1) << 3) + rr;   // row within 16-row block
  const int g2 = g >> 1;                  // k-half chunk
  const int rowA = wm * 64 + grow;
  const int rowB = wn * 32 + grow;
  const uint32_t offA = (uint32_t)(rowA * 64 + ((g2 ^ ((rowA >> 1) & 3)) << 4));
  const uint32_t offB = (uint32_t)(rowB * 64 + ((g2 ^ ((rowB >> 1) & 3)) << 4));

  float acc[4][4][4] = {};  // [mt][nt][reg]

  constexpr int NITER = KDIM / 32;
#pragma unroll
  for (int s = 0; s < NSTAGE - 1; ++s) {
    load_stage(smem + s * STAGE_BYTES, Ah, Al, Bh, Bl, KDIM, s * 32, tid);
    CP_COMMIT();
  }

#pragma unroll 1
  for (int i = 0; i < NITER; ++i) {
    CP_WAIT2();
    __syncthreads();
    if (i + NSTAGE - 1 < NITER)
      load_stage(smem + ((i + NSTAGE - 1) & (NSTAGE - 1)) * STAGE_BYTES, Ah, Al,
                 Bh, Bl, KDIM, (i + NSTAGE - 1) * 32, tid);
    CP_COMMIT();

    const uint32_t stg = smem + (i & (NSTAGE - 1)) * STAGE_BYTES;
    const uint32_t aH = stg + OFF_AH + offA, aL = stg + OFF_AL + offA;
    const uint32_t bH = stg + OFF_BH + offB, bL = stg + OFF_BL + offB;
#pragma unroll
    for (int kk = 0; kk < 2; ++kk) {
      const uint32_t kx = kk << 5;  // swizzle-safe k-step: addr ^ 32
      uint32_t a_h[4][4], a_l[4][4], b_h[4][2], b_l[4][2];
#pragma unroll
      for (int mt = 0; mt < 4; ++mt) {
        LDSM4(a_h[mt][0], a_h[mt][1], a_h[mt][2], a_h[mt][3],
              (aH + mt * 1024) ^ kx);
        LDSM4(a_l[mt][0], a_l[mt][1], a_l[mt][2], a_l[mt][3],
              (aL + mt * 1024) ^ kx);
      }
#pragma unroll
      for (int p = 0; p < 2; ++p) {
        uint32_t r0, r1, r2, r3;
        LDSM4(r0, r1, r2, r3, (bH + p * 1024) ^ kx);
        b_h[2 * p][0] = r0; b_h[2 * p + 1][0] = r1;
        b_h[2 * p][1] = r2; b_h[2 * p + 1][1] = r3;
        LDSM4(r0, r1, r2, r3, (bL + p * 1024) ^ kx);
        b_l[2 * p][0] = r0; b_l[2 * p + 1][0] = r1;
        b_l[2 * p][1] = r2; b_l[2 * p + 1][1] = r3;
      }
#pragma unroll
      for (int mt = 0; mt < 4; ++mt)
#pragma unroll
        for (int nt = 0; nt < 4; ++nt) {
          mma16816(acc[mt][nt], a_h[mt], b_h[nt]);
          mma16816(acc[mt][nt], a_h[mt], b_l[nt]);
          mma16816(acc[mt][nt], a_l[mt], b_h[nt]);
        }
    }
    __syncthreads();
  }

  // epilogue: c0,c1 -> (row, col..col+1), c2,c3 -> (row+8, col..col+1)
  const int erow = (lane >> 2), ecol = (lane & 3) * 2;
  float* Cb = C + (size_t)b * cBatch;
#pragma unroll
  for (int mt = 0; mt < 4; ++mt) {
#pragma unroll
    for (int nt = 0; nt < 4; ++nt) {
      int row = m0 + wm * 64 + mt * 16 + erow;
      int col = n0 + wn * 32 + nt * 8 + ecol;
      *(float2*)(Cb + (size_t)row * LDC + col) =
          make_float2(acc[mt][nt][0], acc[mt][nt][1]);
      *(float2*)(Cb + (size_t)(row + 8) * LDC + col) =
          make_float2(acc[mt][nt][2], acc[mt][nt][3]);
    }
  }
}

__global__ __launch_bounds__(256, 1) void qk_mma() {
  mma_body<DIM, LK>(g_Qh, g_Ql, g_Kh, g_Kl, g_S, (size_t)LQ * DIM,
                    (size_t)LK * DIM, (size_t)LQ * LK);
}

__global__ __launch_bounds__(256, 1) void pv_mma(float* __restrict__ O) {
  mma_body<LK, DIM>(g_Ph, g_Pl, g_Kth, g_Ktl, O, (size_t)LQ * LK,
                    (size_t)DIM * LK, (size_t)LQ * DIM);
}

// ---------------- softmax: S (fp32) -> Ph/Pl (split bf16) ----------------
__global__ __launch_bounds__(256) void softmax_k() {
  const size_t ro = (size_t)blockIdx.x * LK;
  const float* row = g_S + ro;
  bf16* ph = g_Ph + ro;
  bf16* pl = g_Pl + ro;
  const int t = threadIdx.x;

  float v[8];
  float m = -1e30f;
#pragma unroll
  for (int i = 0; i < 8; ++i) {
    v[i] = row[t + 256 * i];
    m = fmaxf(m, v[i]);
  }
  __shared__ float red[32];
#pragma unroll
  for (int o = 16; o; o >>= 1) m = fmaxf(m, __shfl_xor_sync(0xffffffffu, m, o));
  if ((t & 31) == 0) red[t >> 5] = m;
  __syncthreads();
  if (t < 32) {
    float x = (t < 8) ? red[t] : -1e30f;
#pragma unroll
    for (int o = 4; o; o >>= 1) x = fmaxf(x, __shfl_xor_sync(0xffffffffu, x, o));
    if (t == 0) red[0] = x;
  }
  __syncthreads();
  m = red[0];

  float s = 0.f;
#pragma unroll
  for (int i = 0; i < 8; ++i) {
    v[i] = __expf(v[i] - m);
    s += v[i];
  }
#pragma unroll
  for (int o = 16; o; o >>= 1) s += __shfl_xor_sync(0xffffffffu, s, o);
  __syncthreads();
  if ((t & 31) == 0) red[t >> 5] = s;
  __syncthreads();
  if (t < 32) {
    float x = (t < 8) ? red[t] : 0.f;
#pragma unroll
    for (int o = 4; o; o >>= 1) x += __shfl_xor_sync(0xffffffffu, x, o);
    if (t == 0) red[1] = x;
  }
  __syncthreads();
  const float inv = 1.f / red[1];
#pragma unroll
  for (int i = 0; i < 8; ++i) {
    float p = v[i] * inv;
    bf16 h = __float2bfloat16(p);
    ph[t + 256 * i] = h;
    pl[t + 256 * i] = __float2bfloat16(p - __bfloat162float(h));
  }
}

// ---------------- launch ----------------
extern "C" void kernel_launch(void* const* d_in, const int* in_sizes, int n_in,
                              void* d_out, int out_size) {
  const float* Q = (const float*)d_in[0];
  const float* K = (const float*)d_in[1];
  float* O = (float*)d_out;

  cudaFuncSetAttribute(qk_mma, cudaFuncAttributeMaxDynamicSharedMemorySize,
                       SMEM_ALLOC);
  cudaFuncSetAttribute(pv_mma, cudaFuncAttributeMaxDynamicSharedMemorySize,
                       SMEM_ALLOC);

  convert_q<<<(int)(((size_t)BATCH * LQ * DIM / 4) / 256), 256>>>(
      (const float4*)Q);
  convert_kt<<<dim3(DIM / 32, LK / 32, BATCH), dim3(32, 8)>>>(K);
  qk_mma<<<dim3(LK / 128, LQ / 128, BATCH), 256, SMEM_ALLOC>>>();
  softmax_k<<<BATCH * LQ, 256>>>();
  pv_mma<<<dim3(DIM / 128, LQ / 128, BATCH), 256, SMEM_ALLOC>>>(O);
}

// round 6
// speedup vs baseline: 4.1239x; 1.5583x over previous
#include <cuda_runtime.h>
#include <cuda_fp16.h>
#include <cstdint>

#define BATCH 16
#define LQ 1024
#define LK 2048
#define DIM 4096

// ---------------- scratch (static device allocations) ----------------
__device__ __half g_Qh[(size_t)BATCH * LQ * DIM];   // 128 MiB
__device__ __half g_Ql[(size_t)BATCH * LQ * DIM];   // 128 MiB
__device__ __half g_Kh[(size_t)BATCH * LK * DIM];   // 256 MiB
__device__ __half g_Kl[(size_t)BATCH * LK * DIM];   // 256 MiB
__device__ __half g_Kth[(size_t)BATCH * DIM * LK];  // 256 MiB (K^T, f16)
__device__ float g_S[(size_t)BATCH * LQ * LK];      // 128 MiB
__device__ __half g_Ph[(size_t)BATCH * LQ * LK];    // 64 MiB

// ---------------- helpers ----------------
__device__ __forceinline__ uint32_t smem_u32(const void* p) {
  uint32_t a;
  asm("{ .reg .u64 t; cvta.to.shared.u64 t, %1; cvt.u32.u64 %0, t; }"
      : "=r"(a) : "l"(p));
  return a;
}
__device__ __forceinline__ void cp16(uint32_t s, const void* g) {
  asm volatile("cp.async.cg.shared.global [%0], [%1], 16;" :: "r"(s), "l"(g));
}
#define CP_COMMIT() asm volatile("cp.async.commit_group;" ::: "memory")
#define CP_WAIT2()  asm volatile("cp.async.wait_group 2;" ::: "memory")

#define LDSM4(R0, R1, R2, R3, A)                                              \
  asm volatile("ldmatrix.sync.aligned.m8n8.x4.shared.b16 {%0,%1,%2,%3}, [%4];"\
               : "=r"(R0), "=r"(R1), "=r"(R2), "=r"(R3) : "r"(A))

__device__ __forceinline__ void mma_f32acc(float* c, const uint32_t* a,
                                           const uint32_t* b) {
  asm volatile(
      "mma.sync.aligned.m16n8k16.row.col.f32.f16.f16.f32 "
      "{%0,%1,%2,%3}, {%4,%5,%6,%7}, {%8,%9}, {%0,%1,%2,%3};"
      : "+f"(c[0]), "+f"(c[1]), "+f"(c[2]), "+f"(c[3])
      : "r"(a[0]), "r"(a[1]), "r"(a[2]), "r"(a[3]), "r"(b[0]), "r"(b[1]));
}
__device__ __forceinline__ void mma_f16acc(uint32_t* c, const uint32_t* a,
                                           const uint32_t* b) {
  asm volatile(
      "mma.sync.aligned.m16n8k16.row.col.f16.f16.f16.f16 "
      "{%0,%1}, {%2,%3,%4,%5}, {%6,%7}, {%0,%1};"
      : "+r"(c[0]), "+r"(c[1])
      : "r"(a[0]), "r"(a[1]), "r"(a[2]), "r"(a[3]), "r"(b[0]), "r"(b[1]));
}

// ---------------- conversion kernels ----------------
__global__ __launch_bounds__(256) void convert_q(const float4* __restrict__ Q) {
  size_t i = (size_t)blockIdx.x * 256 + threadIdx.x;
  float4 v = Q[i];
  float f[4] = {v.x, v.y, v.z, v.w};
  __half h[4], l[4];
#pragma unroll
  for (int j = 0; j < 4; ++j) {
    h[j] = __float2half_rn(f[j]);
    l[j] = __float2half_rn(f[j] - __half2float(h[j]));
  }
  *(uint2*)(g_Qh + 4 * i) = *(uint2*)h;
  *(uint2*)(g_Ql + 4 * i) = *(uint2*)l;
}

// K -> Kh/Kl (row-major) and Kth (transposed [d][k], f16 only)
__global__ __launch_bounds__(256) void convert_kt(const float* __restrict__ K) {
  __shared__ float tile[32][33];
  const int b = blockIdx.z, k0 = blockIdx.y * 32, d0 = blockIdx.x * 32;
  const float* Kb = K + (size_t)b * LK * DIM;
  __half* Khb = g_Kh + (size_t)b * LK * DIM;
  __half* Klb = g_Kl + (size_t)b * LK * DIM;
  __half* Kthb = g_Kth + (size_t)b * DIM * LK;
  const int tx = threadIdx.x, ty = threadIdx.y;
#pragma unroll
  for (int i = 0; i < 4; ++i) {
    int k = k0 + ty + 8 * i;
    float v = Kb[(size_t)k * DIM + d0 + tx];
    __half h = __float2half_rn(v);
    Khb[(size_t)k * DIM + d0 + tx] = h;
    Klb[(size_t)k * DIM + d0 + tx] = __float2half_rn(v - __half2float(h));
    tile[ty + 8 * i][tx] = v;
  }
  __syncthreads();
#pragma unroll
  for (int i = 0; i < 4; ++i) {
    int d = d0 + ty + 8 * i;
    Kthb[(size_t)d * LK + k0 + tx] = __float2half_rn(tile[tx][ty + 8 * i]);
  }
}

// =====================================================================
// QK GEMM: S = (Qh+Ql)·(Kh+Kl)^T, 3 products; hh in f32-acc, hl/lh in
// f16-acc. CTA 128x128, BK=32, 8 warps (2M x 4N of 64x32), 4-stage.
// =====================================================================
#define QK_OFF_AH 0
#define QK_OFF_AL 8192
#define QK_OFF_BH 16384
#define QK_OFF_BL 24576
#define QK_STAGE 32768
#define QK_SMEM (4 * QK_STAGE)

__device__ __forceinline__ void qk_load_stage(uint32_t stg, const __half* Ah,
                                              const __half* Al,
                                              const __half* Bh,
                                              const __half* Bl, int koff,
                                              int tid) {
#pragma unroll
  for (int it = 0; it < 2; ++it) {
    int idx = tid + 256 * it;  // 512 = 128 rows x 4 chunks(16B)
    int r = idx >> 2, c = idx & 3;
    uint32_t so = (uint32_t)(r * 64 + ((c ^ ((r >> 1) & 3)) << 4));
    size_t go = (size_t)r * DIM + koff + c * 8;
    cp16(stg + QK_OFF_AH + so, Ah + go);
    cp16(stg + QK_OFF_AL + so, Al + go);
    cp16(stg + QK_OFF_BH + so, Bh + go);
    cp16(stg + QK_OFF_BL + so, Bl + go);
  }
}

__global__ __launch_bounds__(256, 1) void qk_mma() {
  extern __shared__ char smem_raw[];
  const uint32_t smem = smem_u32(smem_raw);
  const int tid = threadIdx.x;
  const int lane = tid & 31, wid = tid >> 5;
  const int wm = wid & 1, wn = wid >> 1;
  const int b = blockIdx.z;
  const int n0 = blockIdx.x * 128, m0 = blockIdx.y * 128;

  const __half* Ah = g_Qh + (size_t)b * LQ * DIM + (size_t)m0 * DIM;
  const __half* Al = g_Ql + (size_t)b * LQ * DIM + (size_t)m0 * DIM;
  const __half* Bh = g_Kh + (size_t)b * LK * DIM + (size_t)n0 * DIM;
  const __half* Bl = g_Kl + (size_t)b * LK * DIM + (size_t)n0 * DIM;

  const int g = lane >> 3, rr = lane & 7;
  const int grow = ((g & 1) << 3) + rr;
  const int g2 = g >> 1;
  const int rowA = wm * 64 + grow;
  const int rowB = wn * 32 + grow;
  const uint32_t offA = (uint32_t)(rowA * 64 + ((g2 ^ ((rowA >> 1) & 3)) << 4));
  const uint32_t offB = (uint32_t)(rowB * 64 + ((g2 ^ ((rowB >> 1) & 3)) << 4));

  float acc[4][4][4] = {};
  uint32_t cacc[4][4][2] = {};  // f16x2 correction accumulators

  constexpr int NITER = DIM / 32;
#pragma unroll
  for (int s = 0; s < 3; ++s) {
    qk_load_stage(smem + s * QK_STAGE, Ah, Al, Bh, Bl, s * 32, tid);
    CP_COMMIT();
  }

#pragma unroll 1
  for (int i = 0; i < NITER; ++i) {
    CP_WAIT2();
    __syncthreads();
    if (i + 3 < NITER)
      qk_load_stage(smem + ((i + 3) & 3) * QK_STAGE, Ah, Al, Bh, Bl,
                    (i + 3) * 32, tid);
    CP_COMMIT();

    const uint32_t stg = smem + (i & 3) * QK_STAGE;
    const uint32_t aH = stg + QK_OFF_AH + offA, aL = stg + QK_OFF_AL + offA;
    const uint32_t bH = stg + QK_OFF_BH + offB, bL = stg + QK_OFF_BL + offB;
#pragma unroll
    for (int kk = 0; kk < 2; ++kk) {
      const uint32_t kx = kk << 5;
      uint32_t a_h[4][4], a_l[4][4], b_h[4][2], b_l[4][2];
#pragma unroll
      for (int mt = 0; mt < 4; ++mt) {
        LDSM4(a_h[mt][0], a_h[mt][1], a_h[mt][2], a_h[mt][3],
              (aH + mt * 1024) ^ kx);
        LDSM4(a_l[mt][0], a_l[mt][1], a_l[mt][2], a_l[mt][3],
              (aL + mt * 1024) ^ kx);
      }
#pragma unroll
      for (int p = 0; p < 2; ++p) {
        uint32_t r0, r1, r2, r3;
        LDSM4(r0, r1, r2, r3, (bH + p * 1024) ^ kx);
        b_h[2 * p][0] = r0; b_h[2 * p + 1][0] = r1;
        b_h[2 * p][1] = r2; b_h[2 * p + 1][1] = r3;
        LDSM4(r0, r1, r2, r3, (bL + p * 1024) ^ kx);
        b_l[2 * p][0] = r0; b_l[2 * p + 1][0] = r1;
        b_l[2 * p][1] = r2; b_l[2 * p + 1][1] = r3;
      }
#pragma unroll
      for (int mt = 0; mt < 4; ++mt)
#pragma unroll
        for (int nt = 0; nt < 4; ++nt) {
          mma_f32acc(acc[mt][nt], a_h[mt], b_h[nt]);
          mma_f16acc(cacc[mt][nt], a_h[mt], b_l[nt]);
          mma_f16acc(cacc[mt][nt], a_l[mt], b_h[nt]);
        }
    }
    __syncthreads();
  }

  const int erow = (lane >> 2), ecol = (lane & 3) * 2;
  float* Cb = g_S + (size_t)b * LQ * LK;
#pragma unroll
  for (int mt = 0; mt < 4; ++mt) {
#pragma unroll
    for (int nt = 0; nt < 4; ++nt) {
      int row = m0 + wm * 64 + mt * 16 + erow;
      int col = n0 + wn * 32 + nt * 8 + ecol;
      float2 c0 = __half22float2(*(__half2*)&cacc[mt][nt][0]);
      float2 c1 = __half22float2(*(__half2*)&cacc[mt][nt][1]);
      *(float2*)(Cb + (size_t)row * LK + col) =
          make_float2(acc[mt][nt][0] + c0.x, acc[mt][nt][1] + c0.y);
      *(float2*)(Cb + (size_t)(row + 8) * LK + col) =
          make_float2(acc[mt][nt][2] + c1.x, acc[mt][nt][3] + c1.y);
    }
  }
}

// =====================================================================
// PV GEMM: O = Ph·Kth^T, SINGLE f16 product (f32 acc).
// CTA 128x128, BK=32, 4-stage x 16KB = 64KB -> 2 CTAs/SM.
// =====================================================================
#define PV_OFF_A 0
#define PV_OFF_B 8192
#define PV_STAGE 16384
#define PV_SMEM (4 * PV_STAGE)

__device__ __forceinline__ void pv_load_stage(uint32_t stg, const __half* A,
                                              const __half* B, int koff,
                                              int tid) {
#pragma unroll
  for (int it = 0; it < 2; ++it) {
    int idx = tid + 256 * it;
    int r = idx >> 2, c = idx & 3;
    uint32_t so = (uint32_t)(r * 64 + ((c ^ ((r >> 1) & 3)) << 4));
    size_t go = (size_t)r * LK + koff + c * 8;
    cp16(stg + PV_OFF_A + so, A + go);
    cp16(stg + PV_OFF_B + so, B + go);
  }
}

__global__ __launch_bounds__(256, 2) void pv_mma(float* __restrict__ O) {
  extern __shared__ char smem_raw[];
  const uint32_t smem = smem_u32(smem_raw);
  const int tid = threadIdx.x;
  const int lane = tid & 31, wid = tid >> 5;
  const int wm = wid & 1, wn = wid >> 1;
  const int b = blockIdx.z;
  const int n0 = blockIdx.x * 128, m0 = blockIdx.y * 128;

  const __half* A = g_Ph + (size_t)b * LQ * LK + (size_t)m0 * LK;
  const __half* B = g_Kth + (size_t)b * DIM * LK + (size_t)n0 * LK;

  const int g = lane >> 3, rr = lane & 7;
  const int grow = ((g & 1) << 3) + rr;
  const int g2 = g >> 1;
  const int rowA = wm * 64 + grow;
  const int rowB = wn * 32 + grow;
  const uint32_t offA = (uint32_t)(rowA * 64 + ((g2 ^ ((rowA >> 1) & 3)) << 4));
  const uint32_t offB = (uint32_t)(rowB * 64 + ((g2 ^ ((rowB >> 1) & 3)) << 4));

  float acc[4][4][4] = {};

  constexpr int NITER = LK / 32;
#pragma unroll
  for (int s = 0; s < 3; ++s) {
    pv_load_stage(smem + s * PV_STAGE, A, B, s * 32, tid);
    CP_COMMIT();
  }

#pragma unroll 1
  for (int i = 0; i < NITER; ++i) {
    CP_WAIT2();
    __syncthreads();
    if (i + 3 < NITER)
      pv_load_stage(smem + ((i + 3) & 3) * PV_STAGE, A, B, (i + 3) * 32, tid);
    CP_COMMIT();

    const uint32_t stg = smem + (i & 3) * PV_STAGE;
    const uint32_t aP = stg + PV_OFF_A + offA, bP = stg + PV_OFF_B + offB;
#pragma unroll
    for (int kk = 0; kk < 2; ++kk) {
      const uint32_t kx = kk << 5;
      uint32_t a[4][4], bb[4][2];
#pragma unroll
      for (int mt = 0; mt < 4; ++mt)
        LDSM4(a[mt][0], a[mt][1], a[mt][2], a[mt][3], (aP + mt * 1024) ^ kx);
#pragma unroll
      for (int p = 0; p < 2; ++p) {
        uint32_t r0, r1, r2, r3;
        LDSM4(r0, r1, r2, r3, (bP + p * 1024) ^ kx);
        bb[2 * p][0] = r0; bb[2 * p + 1][0] = r1;
        bb[2 * p][1] = r2; bb[2 * p + 1][1] = r3;
      }
#pragma unroll
      for (int mt = 0; mt < 4; ++mt)
#pragma unroll
        for (int nt = 0; nt < 4; ++nt)
          mma_f32acc(acc[mt][nt], a[mt], bb[nt]);
    }
    __syncthreads();
  }

  const int erow = (lane >> 2), ecol = (lane & 3) * 2;
  float* Cb = O + (size_t)b * LQ * DIM;
#pragma unroll
  for (int mt = 0; mt < 4; ++mt) {
#pragma unroll
    for (int nt = 0; nt < 4; ++nt) {
      int row = m0 + wm * 64 + mt * 16 + erow;
      int col = n0 + wn * 32 + nt * 8 + ecol;
      *(float2*)(Cb + (size_t)row * DIM + col) =
          make_float2(acc[mt][nt][0], acc[mt][nt][1]);
      *(float2*)(Cb + (size_t)(row + 8) * DIM + col) =
          make_float2(acc[mt][nt][2], acc[mt][nt][3]);
    }
  }
}

// ---------------- softmax: S (fp32) -> Ph (f16) ----------------
__global__ __launch_bounds__(256) void softmax_k() {
  const size_t ro = (size_t)blockIdx.x * LK;
  const float* row = g_S + ro;
  __half* ph = g_Ph + ro;
  const int t = threadIdx.x;

  float v[8];
  float m = -1e30f;
#pragma unroll
  for (int i = 0; i < 8; ++i) {
    v[i] = row[t + 256 * i];
    m = fmaxf(m, v[i]);
  }
  __shared__ float red[32];
#pragma unroll
  for (int o = 16; o; o >>= 1) m = fmaxf(m, __shfl_xor_sync(0xffffffffu, m, o));
  if ((t & 31) == 0) red[t >> 5] = m;
  __syncthreads();
  if (t < 32) {
    float x = (t < 8) ? red[t] : -1e30f;
#pragma unroll
    for (int o = 4; o; o >>= 1) x = fmaxf(x, __shfl_xor_sync(0xffffffffu, x, o));
    if (t == 0) red[0] = x;
  }
  __syncthreads();
  m = red[0];

  float s = 0.f;
#pragma unroll
  for (int i = 0; i < 8; ++i) {
    v[i] = __expf(v[i] - m);
    s += v[i];
  }
#pragma unroll
  for (int o = 16; o; o >>= 1) s += __shfl_xor_sync(0xffffffffu, s, o);
  __syncthreads();
  if ((t & 31) == 0) red[t >> 5] = s;
  __syncthreads();
  if (t < 32) {
    float x = (t < 8) ? red[t] : 0.f;
#pragma unroll
    for (int o = 4; o; o >>= 1) x += __shfl_xor_sync(0xffffffffu, x, o);
    if (t == 0) red[1] = x;
  }
  __syncthreads();
  const float inv = 1.f / red[1];
#pragma unroll
  for (int i = 0; i < 8; ++i) ph[t + 256 * i] = __float2half_rn(v[i] * inv);
}

// ---------------- launch ----------------
extern "C" void kernel_launch(void* const* d_in, const int* in_sizes, int n_in,
                              void* d_out, int out_size) {
  const float* Q = (const float*)d_in[0];
  const float* K = (const float*)d_in[1];
  float* O = (float*)d_out;

  cudaFuncSetAttribute(qk_mma, cudaFuncAttributeMaxDynamicSharedMemorySize,
                       QK_SMEM);
  cudaFuncSetAttribute(pv_mma, cudaFuncAttributeMaxDynamicSharedMemorySize,
                       PV_SMEM);

  convert_q<<<(int)(((size_t)BATCH * LQ * DIM / 4) / 256), 256>>>(
      (const float4*)Q);
  convert_kt<<<dim3(DIM / 32, LK / 32, BATCH), dim3(32, 8)>>>(K);
  qk_mma<<<dim3(LK / 128, LQ / 128, BATCH), 256, QK_SMEM>>>();
  softmax_k<<<BATCH * LQ, 256>>>();
  pv_mma<<<dim3(DIM / 128, LQ / 128, BATCH), 256, PV_SMEM>>>(O);
}

// round 7
// speedup vs baseline: 4.1245x; 1.0001x over previous
#include <cuda_runtime.h>
#include <cuda_fp16.h>
#include <cstdint>

#define BATCH 16
#define LQ 1024
#define LK 2048
#define DIM 4096

// ---------------- scratch (static device allocations) ----------------
__device__ __half g_Qh[(size_t)BATCH * LQ * DIM];   // 128 MiB
__device__ __half g_Ql[(size_t)BATCH * LQ * DIM];   // 128 MiB
__device__ __half g_Kh[(size_t)BATCH * LK * DIM];   // 256 MiB
__device__ __half g_Kl[(size_t)BATCH * LK * DIM];   // 256 MiB
__device__ __half g_Kth[(size_t)BATCH * DIM * LK];  // 256 MiB (K^T, f16)
__device__ float g_S[(size_t)BATCH * LQ * LK];      // 128 MiB
__device__ __half g_Ph[(size_t)BATCH * LQ * LK];    // 64 MiB

// ---------------- helpers ----------------
__device__ __forceinline__ uint32_t smem_u32(const void* p) {
  uint32_t a;
  asm("{ .reg .u64 t; cvta.to.shared.u64 t, %1; cvt.u32.u64 %0, t; }"
      : "=r"(a) : "l"(p));
  return a;
}
__device__ __forceinline__ void cp16(uint32_t s, const void* g) {
  asm volatile("cp.async.cg.shared.global [%0], [%1], 16;" :: "r"(s), "l"(g));
}
#define CP_COMMIT() asm volatile("cp.async.commit_group;" ::: "memory")
#define CP_WAIT2()  asm volatile("cp.async.wait_group 2;" ::: "memory")

#define LDSM4(R0, R1, R2, R3, A)                                              \
  asm volatile("ldmatrix.sync.aligned.m8n8.x4.shared.b16 {%0,%1,%2,%3}, [%4];"\
               : "=r"(R0), "=r"(R1), "=r"(R2), "=r"(R3) : "r"(A))

__device__ __forceinline__ void mma_f32acc(float* c, const uint32_t* a,
                                           const uint32_t* b) {
  asm volatile(
      "mma.sync.aligned.m16n8k16.row.col.f32.f16.f16.f32 "
      "{%0,%1,%2,%3}, {%4,%5,%6,%7}, {%8,%9}, {%0,%1,%2,%3};"
      : "+f"(c[0]), "+f"(c[1]), "+f"(c[2]), "+f"(c[3])
      : "r"(a[0]), "r"(a[1]), "r"(a[2]), "r"(a[3]), "r"(b[0]), "r"(b[1]));
}
__device__ __forceinline__ void mma_f16acc(uint32_t* c, const uint32_t* a,
                                           const uint32_t* b) {
  asm volatile(
      "mma.sync.aligned.m16n8k16.row.col.f16.f16.f16.f16 "
      "{%0,%1}, {%2,%3,%4,%5}, {%6,%7}, {%0,%1};"
      : "+r"(c[0]), "+r"(c[1])
      : "r"(a[0]), "r"(a[1]), "r"(a[2]), "r"(a[3]), "r"(b[0]), "r"(b[1]));
}

// ---------------- conversion kernels ----------------
__global__ __launch_bounds__(256) void convert_q(const float4* __restrict__ Q) {
  size_t i = (size_t)blockIdx.x * 256 + threadIdx.x;
  float4 v = Q[i];
  float f[4] = {v.x, v.y, v.z, v.w};
  __half h[4], l[4];
#pragma unroll
  for (int j = 0; j < 4; ++j) {
    h[j] = __float2half_rn(f[j]);
    l[j] = __float2half_rn(f[j] - __half2float(h[j]));
  }
  *(uint2*)(g_Qh + 4 * i) = *(uint2*)h;
  *(uint2*)(g_Ql + 4 * i) = *(uint2*)l;
}

// K -> Kh/Kl (row-major) and Kth (transposed [d][k], f16 only)
__global__ __launch_bounds__(256) void convert_kt(const float* __restrict__ K) {
  __shared__ float tile[32][33];
  const int b = blockIdx.z, k0 = blockIdx.y * 32, d0 = blockIdx.x * 32;
  const float* Kb = K + (size_t)b * LK * DIM;
  __half* Khb = g_Kh + (size_t)b * LK * DIM;
  __half* Klb = g_Kl + (size_t)b * LK * DIM;
  __half* Kthb = g_Kth + (size_t)b * DIM * LK;
  const int tx = threadIdx.x, ty = threadIdx.y;
#pragma unroll
  for (int i = 0; i < 4; ++i) {
    int k = k0 + ty + 8 * i;
    float v = Kb[(size_t)k * DIM + d0 + tx];
    __half h = __float2half_rn(v);
    Khb[(size_t)k * DIM + d0 + tx] = h;
    Klb[(size_t)k * DIM + d0 + tx] = __float2half_rn(v - __half2float(h));
    tile[ty + 8 * i][tx] = v;
  }
  __syncthreads();
#pragma unroll
  for (int i = 0; i < 4; ++i) {
    int d = d0 + ty + 8 * i;
    Kthb[(size_t)d * LK + k0 + tx] = __float2half_rn(tile[tx][ty + 8 * i]);
  }
}

// =====================================================================
// QK GEMM: S = (Qh+Ql)·(Kh+Kl)^T, 3 products (hh f32-acc; hl/lh f16-acc)
// issued PRODUCT-MAJOR so dependent cacc MMAs are 16 apart (no RAW stall).
// CTA 128x128, BK=32, 8 warps (2M x 4N of 64x32), 4-stage cp.async.
// =====================================================================
#define QK_OFF_AH 0
#define QK_OFF_AL 8192
#define QK_OFF_BH 16384
#define QK_OFF_BL 24576
#define QK_STAGE 32768
#define QK_SMEM (4 * QK_STAGE)

__device__ __forceinline__ void qk_load_stage(uint32_t stg, const __half* Ah,
                                              const __half* Al,
                                              const __half* Bh,
                                              const __half* Bl, int koff,
                                              int tid) {
#pragma unroll
  for (int it = 0; it < 2; ++it) {
    int idx = tid + 256 * it;  // 512 = 128 rows x 4 chunks(16B)
    int r = idx >> 2, c = idx & 3;
    uint32_t so = (uint32_t)(r * 64 + ((c ^ ((r >> 1) & 3)) << 4));
    size_t go = (size_t)r * DIM + koff + c * 8;
    cp16(stg + QK_OFF_AH + so, Ah + go);
    cp16(stg + QK_OFF_AL + so, Al + go);
    cp16(stg + QK_OFF_BH + so, Bh + go);
    cp16(stg + QK_OFF_BL + so, Bl + go);
  }
}

__global__ __launch_bounds__(256, 1) void qk_mma() {
  extern __shared__ char smem_raw[];
  const uint32_t smem = smem_u32(smem_raw);
  const int tid = threadIdx.x;
  const int lane = tid & 31, wid = tid >> 5;
  const int wm = wid & 1, wn = wid >> 1;
  const int b = blockIdx.z;
  const int n0 = blockIdx.x * 128, m0 = blockIdx.y * 128;

  const __half* Ah = g_Qh + (size_t)b * LQ * DIM + (size_t)m0 * DIM;
  const __half* Al = g_Ql + (size_t)b * LQ * DIM + (size_t)m0 * DIM;
  const __half* Bh = g_Kh + (size_t)b * LK * DIM + (size_t)n0 * DIM;
  const __half* Bl = g_Kl + (size_t)b * LK * DIM + (size_t)n0 * DIM;

  const int g = lane >> 3, rr = lane & 7;
  const int grow = ((g & 1) << 3) + rr;
  const int g2 = g >> 1;
  const int rowA = wm * 64 + grow;
  const int rowB = wn * 32 + grow;
  const uint32_t offA = (uint32_t)(rowA * 64 + ((g2 ^ ((rowA >> 1) & 3)) << 4));
  const uint32_t offB = (uint32_t)(rowB * 64 + ((g2 ^ ((rowB >> 1) & 3)) << 4));

  float acc[4][4][4] = {};
  uint32_t cacc[4][4][2] = {};  // f16x2 correction accumulators

  constexpr int NITER = DIM / 32;
#pragma unroll
  for (int s = 0; s < 3; ++s) {
    qk_load_stage(smem + s * QK_STAGE, Ah, Al, Bh, Bl, s * 32, tid);
    CP_COMMIT();
  }

#pragma unroll 1
  for (int i = 0; i < NITER; ++i) {
    CP_WAIT2();
    __syncthreads();
    if (i + 3 < NITER)
      qk_load_stage(smem + ((i + 3) & 3) * QK_STAGE, Ah, Al, Bh, Bl,
                    (i + 3) * 32, tid);
    CP_COMMIT();

    const uint32_t stg = smem + (i & 3) * QK_STAGE;
    const uint32_t aH = stg + QK_OFF_AH + offA, aL = stg + QK_OFF_AL + offA;
    const uint32_t bH = stg + QK_OFF_BH + offB, bL = stg + QK_OFF_BL + offB;
#pragma unroll
    for (int kk = 0; kk < 2; ++kk) {
      const uint32_t kx = kk << 5;
      uint32_t a_h[4][4], a_l[4][4], b_h[4][2], b_l[4][2];
#pragma unroll
      for (int mt = 0; mt < 4; ++mt) {
        LDSM4(a_h[mt][0], a_h[mt][1], a_h[mt][2], a_h[mt][3],
              (aH + mt * 1024) ^ kx);
        LDSM4(a_l[mt][0], a_l[mt][1], a_l[mt][2], a_l[mt][3],
              (aL + mt * 1024) ^ kx);
      }
#pragma unroll
      for (int p = 0; p < 2; ++p) {
        uint32_t r0, r1, r2, r3;
        LDSM4(r0, r1, r2, r3, (bH + p * 1024) ^ kx);
        b_h[2 * p][0] = r0; b_h[2 * p + 1][0] = r1;
        b_h[2 * p][1] = r2; b_h[2 * p + 1][1] = r3;
        LDSM4(r0, r1, r2, r3, (bL + p * 1024) ^ kx);
        b_l[2 * p][0] = r0; b_l[2 * p + 1][0] = r1;
        b_l[2 * p][1] = r2; b_l[2 * p + 1][1] = r3;
      }
      // product-major: 16 independent MMAs per block; dependent cacc
      // writes (hl->lh on same tile) are 16 MMAs apart.
#pragma unroll
      for (int mt = 0; mt < 4; ++mt)
#pragma unroll
        for (int nt = 0; nt < 4; ++nt)
          mma_f32acc(acc[mt][nt], a_h[mt], b_h[nt]);
#pragma unroll
      for (int mt = 0; mt < 4; ++mt)
#pragma unroll
        for (int nt = 0; nt < 4; ++nt)
          mma_f16acc(cacc[mt][nt], a_h[mt], b_l[nt]);
#pragma unroll
      for (int mt = 0; mt < 4; ++mt)
#pragma unroll
        for (int nt = 0; nt < 4; ++nt)
          mma_f16acc(cacc[mt][nt], a_l[mt], b_h[nt]);
    }
    __syncthreads();
  }

  const int erow = (lane >> 2), ecol = (lane & 3) * 2;
  float* Cb = g_S + (size_t)b * LQ * LK;
#pragma unroll
  for (int mt = 0; mt < 4; ++mt) {
#pragma unroll
    for (int nt = 0; nt < 4; ++nt) {
      int row = m0 + wm * 64 + mt * 16 + erow;
      int col = n0 + wn * 32 + nt * 8 + ecol;
      float2 c0 = __half22float2(*(__half2*)&cacc[mt][nt][0]);
      float2 c1 = __half22float2(*(__half2*)&cacc[mt][nt][1]);
      *(float2*)(Cb + (size_t)row * LK + col) =
          make_float2(acc[mt][nt][0] + c0.x, acc[mt][nt][1] + c0.y);
      *(float2*)(Cb + (size_t)(row + 8) * LK + col) =
          make_float2(acc[mt][nt][2] + c1.x, acc[mt][nt][3] + c1.y);
    }
  }
}

// =====================================================================
// PV GEMM: O = Ph·Kth^T, SINGLE f16 product (f32 acc).
// CTA 128x128, BK=32, 4-stage x 16KB = 64KB -> 2 CTAs/SM.
// =====================================================================
#define PV_OFF_A 0
#define PV_OFF_B 8192
#define PV_STAGE 16384
#define PV_SMEM (4 * PV_STAGE)

__device__ __forceinline__ void pv_load_stage(uint32_t stg, const __half* A,
                                              const __half* B, int koff,
                                              int tid) {
#pragma unroll
  for (int it = 0; it < 2; ++it) {
    int idx = tid + 256 * it;
    int r = idx >> 2, c = idx & 3;
    uint32_t so = (uint32_t)(r * 64 + ((c ^ ((r >> 1) & 3)) << 4));
    size_t go = (size_t)r * LK + koff + c * 8;
    cp16(stg + PV_OFF_A + so, A + go);
    cp16(stg + PV_OFF_B + so, B + go);
  }
}

__global__ __launch_bounds__(256, 2) void pv_mma(float* __restrict__ O) {
  extern __shared__ char smem_raw[];
  const uint32_t smem = smem_u32(smem_raw);
  const int tid = threadIdx.x;
  const int lane = tid & 31, wid = tid >> 5;
  const int wm = wid & 1, wn = wid >> 1;
  const int b = blockIdx.z;
  const int n0 = blockIdx.x * 128, m0 = blockIdx.y * 128;

  const __half* A = g_Ph + (size_t)b * LQ * LK + (size_t)m0 * LK;
  const __half* B = g_Kth + (size_t)b * DIM * LK + (size_t)n0 * LK;

  const int g = lane >> 3, rr = lane & 7;
  const int grow = ((g & 1) << 3) + rr;
  const int g2 = g >> 1;
  const int rowA = wm * 64 + grow;
  const int rowB = wn * 32 + grow;
  const uint32_t offA = (uint32_t)(rowA * 64 + ((g2 ^ ((rowA >> 1) & 3)) << 4));
  const uint32_t offB = (uint32_t)(rowB * 64 + ((g2 ^ ((rowB >> 1) & 3)) << 4));

  float acc[4][4][4] = {};

  constexpr int NITER = LK / 32;
#pragma unroll
  for (int s = 0; s < 3; ++s) {
    pv_load_stage(smem + s * PV_STAGE, A, B, s * 32, tid);
    CP_COMMIT();
  }

#pragma unroll 1
  for (int i = 0; i < NITER; ++i) {
    CP_WAIT2();
    __syncthreads();
    if (i + 3 < NITER)
      pv_load_stage(smem + ((i + 3) & 3) * PV_STAGE, A, B, (i + 3) * 32, tid);
    CP_COMMIT();

    const uint32_t stg = smem + (i & 3) * PV_STAGE;
    const uint32_t aP = stg + PV_OFF_A + offA, bP = stg + PV_OFF_B + offB;
#pragma unroll
    for (int kk = 0; kk < 2; ++kk) {
      const uint32_t kx = kk << 5;
      uint32_t a[4][4], bb[4][2];
#pragma unroll
      for (int mt = 0; mt < 4; ++mt)
        LDSM4(a[mt][0], a[mt][1], a[mt][2], a[mt][3], (aP + mt * 1024) ^ kx);
#pragma unroll
      for (int p = 0; p < 2; ++p) {
        uint32_t r0, r1, r2, r3;
        LDSM4(r0, r1, r2, r3, (bP + p * 1024) ^ kx);
        bb[2 * p][0] = r0; bb[2 * p + 1][0] = r1;
        bb[2 * p][1] = r2; bb[2 * p + 1][1] = r3;
      }
#pragma unroll
      for (int mt = 0; mt < 4; ++mt)
#pragma unroll
        for (int nt = 0; nt < 4; ++nt)
          mma_f32acc(acc[mt][nt], a[mt], bb[nt]);
    }
    __syncthreads();
  }

  const int erow = (lane >> 2), ecol = (lane & 3) * 2;
  float* Cb = O + (size_t)b * LQ * DIM;
#pragma unroll
  for (int mt = 0; mt < 4; ++mt) {
#pragma unroll
    for (int nt = 0; nt < 4; ++nt) {
      int row = m0 + wm * 64 + mt * 16 + erow;
      int col = n0 + wn * 32 + nt * 8 + ecol;
      *(float2*)(Cb + (size_t)row * DIM + col) =
          make_float2(acc[mt][nt][0], acc[mt][nt][1]);
      *(float2*)(Cb + (size_t)(row + 8) * DIM + col) =
          make_float2(acc[mt][nt][2], acc[mt][nt][3]);
    }
  }
}

// ---------------- softmax: S (fp32) -> Ph (f16) ----------------
__global__ __launch_bounds__(256) void softmax_k() {
  const size_t ro = (size_t)blockIdx.x * LK;
  const float* row = g_S + ro;
  __half* ph = g_Ph + ro;
  const int t = threadIdx.x;

  float v[8];
  float m = -1e30f;
#pragma unroll
  for (int i = 0; i < 8; ++i) {
    v[i] = row[t + 256 * i];
    m = fmaxf(m, v[i]);
  }
  __shared__ float red[32];
#pragma unroll
  for (int o = 16; o; o >>= 1) m = fmaxf(m, __shfl_xor_sync(0xffffffffu, m, o));
  if ((t & 31) == 0) red[t >> 5] = m;
  __syncthreads();
  if (t < 32) {
    float x = (t < 8) ? red[t] : -1e30f;
#pragma unroll
    for (int o = 4; o; o >>= 1) x = fmaxf(x, __shfl_xor_sync(0xffffffffu, x, o));
    if (t == 0) red[0] = x;
  }
  __syncthreads();
  m = red[0];

  float s = 0.f;
#pragma unroll
  for (int i = 0; i < 8; ++i) {
    v[i] = __expf(v[i] - m);
    s += v[i];
  }
#pragma unroll
  for (int o = 16; o; o >>= 1) s += __shfl_xor_sync(0xffffffffu, s, o);
  __syncthreads();
  if ((t & 31) == 0) red[t >> 5] = s;
  __syncthreads();
  if (t < 32) {
    float x = (t < 8) ? red[t] : 0.f;
#pragma unroll
    for (int o = 4; o; o >>= 1) x += __shfl_xor_sync(0xffffffffu, x, o);
    if (t == 0) red[1] = x;
  }
  __syncthreads();
  const float inv = 1.f / red[1];
#pragma unroll
  for (int i = 0; i < 8; ++i) ph[t + 256 * i] = __float2half_rn(v[i] * inv);
}

// ---------------- launch ----------------
extern "C" void kernel_launch(void* const* d_in, const int* in_sizes, int n_in,
                              void* d_out, int out_size) {
  const float* Q = (const float*)d_in[0];
  const float* K = (const float*)d_in[1];
  float* O = (float*)d_out;

  cudaFuncSetAttribute(qk_mma, cudaFuncAttributeMaxDynamicSharedMemorySize,
                       QK_SMEM);
  cudaFuncSetAttribute(pv_mma, cudaFuncAttributeMaxDynamicSharedMemorySize,
                       PV_SMEM);

  convert_q<<<(int)(((size_t)BATCH * LQ * DIM / 4) / 256), 256>>>(
      (const float4*)Q);
  convert_kt<<<dim3(DIM / 32, LK / 32, BATCH), dim3(32, 8)>>>(K);
  qk_mma<<<dim3(LK / 128, LQ / 128, BATCH), 256, QK_SMEM>>>();
  softmax_k<<<BATCH * LQ, 256>>>();
  pv_mma<<<dim3(DIM / 128, LQ / 128, BATCH), 256, PV_SMEM>>>(O);
}